// round 1
// baseline (speedup 1.0000x reference)
#include <cuda_runtime.h>
#include <math.h>

// Dead code eliminated from the reference:
//   softmax over a size-1 axis == 1.0  =>  attention output == v
//   => q / Wq / bq / rpb / k-half of Wkv are never needed.
//
// Live pipeline per token (65536 tokens):
//   h = LN(x; g1,b1)                      (C=384)
//   v = h @ Wkv[:,128:256] + bkv[128:]    (384 -> 128)
//   y = v @ Wp + bp                       (128 -> 128)
//   z = y + gelu(LN(y;g2,b2) @ W1 + bm1) @ W2 + bm2   (128->512->128)

#define TM      32      // tokens per CTA
#define NTHR    256
#define CC      384
#define DD      128
#define EPSV    1e-5f

// smem layout (floats):
//   [0,     12288)  h   (32 x 384)   -- aliased by gtile (32 x 128) in stage 5
//   [12288, 16384)  v   (32 x 128)   -- aliased by ln(y)  in stage 4+
//   [16384, 20480)  y   (32 x 128)
//   [20480, 24576)  wbuf(32 x 128)   -- streamed weight chunk
#define OFF_H   0
#define OFF_V   12288
#define OFF_Y   16384
#define OFF_W   20480
#define SMEM_FLOATS 24576
#define SMEM_BYTES  (SMEM_FLOATS * 4)

// Accumulating GEMM: acc[4][4] += A[32][lda] @ W[K][<=ldw] (128-col tile).
// Thread (warp w, lane l) owns rows {w, w+8, w+16, w+24}, cols {4l..4l+3}.
// W element (k, j) read from Wg[k*ldw + j]  (caller pre-offsets Wg for
// column/row windows).
template<int K>
__device__ __forceinline__ void gemm_acc(
    const float* __restrict__ A, int lda,
    const float* __restrict__ Wg, int ldw,
    float* __restrict__ wbuf,
    float acc[4][4],
    int tid, int lane, int warp)
{
    for (int kc = 0; kc < K; kc += 32) {
        __syncthreads();                       // wbuf free to overwrite
        #pragma unroll
        for (int i = 0; i < 16; i++) {         // 32x128 chunk, 16 elems/thread
            int idx = tid + NTHR * i;
            int kk  = idx >> 7;
            int j   = idx & 127;
            wbuf[idx] = Wg[(kc + kk) * ldw + j];
        }
        __syncthreads();                       // wbuf ready
        #pragma unroll 8
        for (int kk = 0; kk < 32; kk++) {
            float4 w4 = *(const float4*)(wbuf + kk * 128 + lane * 4);
            #pragma unroll
            for (int r = 0; r < 4; r++) {
                float a = A[(warp + 8 * r) * lda + kc + kk];   // warp broadcast
                acc[r][0] += a * w4.x;
                acc[r][1] += a * w4.y;
                acc[r][2] += a * w4.z;
                acc[r][3] += a * w4.w;
            }
        }
    }
}

extern __shared__ float smem[];

__global__ void __launch_bounds__(NTHR, 2) fused_kernel(
    const float* __restrict__ x,
    const float* __restrict__ g1, const float* __restrict__ b1,
    const float* __restrict__ Wkv, const float* __restrict__ bkv,
    const float* __restrict__ Wp,  const float* __restrict__ bp,
    const float* __restrict__ g2,  const float* __restrict__ b2,
    const float* __restrict__ W1,  const float* __restrict__ bm1,
    const float* __restrict__ W2,  const float* __restrict__ bm2,
    float* __restrict__ out)
{
    float* sh   = smem + OFF_H;
    float* sv   = smem + OFF_V;
    float* sy   = smem + OFF_Y;
    float* swb  = smem + OFF_W;
    float* sg   = smem + OFF_H;   // gelu tile, aliases h (dead by then)
    float* slny = smem + OFF_V;   // ln(y), aliases v (dead by then)

    const int tid  = threadIdx.x;
    const int lane = tid & 31;
    const int warp = tid >> 5;
    const long tile0 = (long)blockIdx.x * TM;

    // ---------------- Stage 1: h = LN(x) ----------------
    #pragma unroll
    for (int i = 0; i < 4; i++) {
        int r = warp + 8 * i;
        const float* xr = x + (tile0 + r) * CC;
        float vals[12];
        float s = 0.f, ss = 0.f;
        #pragma unroll
        for (int u = 0; u < 12; u++) {
            float t = xr[lane + 32 * u];
            vals[u] = t; s += t; ss += t * t;
        }
        #pragma unroll
        for (int o = 16; o > 0; o >>= 1) {
            s  += __shfl_xor_sync(0xffffffffu, s,  o);
            ss += __shfl_xor_sync(0xffffffffu, ss, o);
        }
        float m  = s * (1.f / 384.f);
        float vr = ss * (1.f / 384.f) - m * m;
        float rs = rsqrtf(vr + EPSV);
        #pragma unroll
        for (int u = 0; u < 12; u++) {
            int k = lane + 32 * u;
            sh[r * CC + k] = (vals[u] - m) * rs * g1[k] + b1[k];
        }
    }
    // (gemm_acc's leading __syncthreads orders sh writes before reads)

    // ---------------- Stage 2: v = h @ Wv + bv ----------------
    float acc[4][4];
    #pragma unroll
    for (int r = 0; r < 4; r++)
        #pragma unroll
        for (int c = 0; c < 4; c++) acc[r][c] = 0.f;

    gemm_acc<384>(sh, CC, Wkv + 128, 256, swb, acc, tid, lane, warp);

    #pragma unroll
    for (int r = 0; r < 4; r++) {
        int row = warp + 8 * r;
        float4 o;
        o.x = acc[r][0] + bkv[128 + lane * 4 + 0];
        o.y = acc[r][1] + bkv[128 + lane * 4 + 1];
        o.z = acc[r][2] + bkv[128 + lane * 4 + 2];
        o.w = acc[r][3] + bkv[128 + lane * 4 + 3];
        *(float4*)(sv + row * DD + lane * 4) = o;
    }

    // ---------------- Stage 3: y = v @ Wp + bp ----------------
    #pragma unroll
    for (int r = 0; r < 4; r++)
        #pragma unroll
        for (int c = 0; c < 4; c++) acc[r][c] = 0.f;

    gemm_acc<128>(sv, DD, Wp, DD, swb, acc, tid, lane, warp);

    #pragma unroll
    for (int r = 0; r < 4; r++) {
        int row = warp + 8 * r;
        float4 o;
        o.x = acc[r][0] + bp[lane * 4 + 0];
        o.y = acc[r][1] + bp[lane * 4 + 1];
        o.z = acc[r][2] + bp[lane * 4 + 2];
        o.w = acc[r][3] + bp[lane * 4 + 3];
        *(float4*)(sy + row * DD + lane * 4) = o;
    }
    __syncthreads();   // sy complete; also: everyone past stage-3 gemm before
                       // slny (aliasing sv) gets overwritten below

    // ---------------- Stage 4: lny = LN(y) ----------------
    #pragma unroll
    for (int i = 0; i < 4; i++) {
        int r = warp + 8 * i;
        float vals[4];
        float s = 0.f, ss = 0.f;
        #pragma unroll
        for (int u = 0; u < 4; u++) {
            float t = sy[r * DD + lane + 32 * u];
            vals[u] = t; s += t; ss += t * t;
        }
        #pragma unroll
        for (int o = 16; o > 0; o >>= 1) {
            s  += __shfl_xor_sync(0xffffffffu, s,  o);
            ss += __shfl_xor_sync(0xffffffffu, ss, o);
        }
        float m  = s * (1.f / 128.f);
        float vr = ss * (1.f / 128.f) - m * m;
        float rs = rsqrtf(vr + EPSV);
        #pragma unroll
        for (int u = 0; u < 4; u++) {
            int k = lane + 32 * u;
            slny[r * DD + k] = (vals[u] - m) * rs * g2[k] + b2[k];
        }
    }

    // ------- Stage 5+6: z = y + gelu(lny @ W1 + bm1) @ W2 + bm2 -------
    float uacc[4][4];
    #pragma unroll
    for (int r = 0; r < 4; r++)
        #pragma unroll
        for (int c = 0; c < 4; c++) uacc[r][c] = 0.f;

    for (int cc = 0; cc < 4; cc++) {           // 512 hidden = 4 tiles of 128
        float tacc[4][4];
        #pragma unroll
        for (int r = 0; r < 4; r++)
            #pragma unroll
            for (int c = 0; c < 4; c++) tacc[r][c] = 0.f;

        gemm_acc<128>(slny, DD, W1 + cc * 128, 512, swb, tacc, tid, lane, warp);

        #pragma unroll
        for (int r = 0; r < 4; r++) {
            int row = warp + 8 * r;
            #pragma unroll
            for (int c = 0; c < 4; c++) {
                int jloc = lane * 4 + c;
                float t = tacc[r][c] + bm1[cc * 128 + jloc];
                float g = 0.5f * t * (1.f + erff(t * 0.70710678118654752f));
                sg[row * DD + jloc] = g;
            }
        }
        // gemm_acc's leading __syncthreads orders sg writes before reads
        gemm_acc<128>(sg, DD, W2 + cc * 128 * 128, DD, swb, uacc, tid, lane, warp);
    }

    // ---------------- Final: z = y + u + bm2 ----------------
    #pragma unroll
    for (int r = 0; r < 4; r++) {
        int row = warp + 8 * r;
        int col = lane * 4;
        float4 o;
        o.x = sy[row * DD + col + 0] + uacc[r][0] + bm2[col + 0];
        o.y = sy[row * DD + col + 1] + uacc[r][1] + bm2[col + 1];
        o.z = sy[row * DD + col + 2] + uacc[r][2] + bm2[col + 2];
        o.w = sy[row * DD + col + 3] + uacc[r][3] + bm2[col + 3];
        *(float4*)(out + (tile0 + row) * DD + col) = o;
    }
}

extern "C" void kernel_launch(void* const* d_in, const int* in_sizes, int n_in,
                              void* d_out, int out_size)
{
    const float* x   = (const float*)d_in[0];
    const float* g1  = (const float*)d_in[1];
    const float* b1  = (const float*)d_in[2];
    // d_in[3] = Wq (dead), d_in[4] = bq (dead)
    const float* Wkv = (const float*)d_in[5];
    const float* bkv = (const float*)d_in[6];
    // d_in[7] = rpb (dead)
    const float* Wp  = (const float*)d_in[8];
    const float* bp  = (const float*)d_in[9];
    const float* g2  = (const float*)d_in[10];
    const float* b2  = (const float*)d_in[11];
    const float* W1  = (const float*)d_in[12];
    const float* bm1 = (const float*)d_in[13];
    const float* W2  = (const float*)d_in[14];
    const float* bm2 = (const float*)d_in[15];
    float* out = (float*)d_out;

    cudaFuncSetAttribute(fused_kernel,
                         cudaFuncAttributeMaxDynamicSharedMemorySize, SMEM_BYTES);

    const int tokens = in_sizes[0] / CC;       // 65536
    const int grid   = tokens / TM;            // 2048
    fused_kernel<<<grid, NTHR, SMEM_BYTES>>>(
        x, g1, b1, Wkv, bkv, Wp, bp, g2, b2, W1, bm1, W2, bm2, out);
}

// round 3
// speedup vs baseline: 3.6275x; 3.6275x over previous
#include <cuda_runtime.h>
#include <math.h>
#include <stdint.h>

// ===========================================================================
// Live math (softmax over size-1 axis == 1 kills q/Wq/bq/rpb/k-half of Wkv):
//   h = LN(x;g1,b1); v = h@Wv+bv; y = v@Wp+bp;
//   z = y + gelu(LN(y;g2,b2)@W1+bm1)@W2 + bm2
// GEMMs on mma.sync m16n8k8 tf32 (HMMA tensor pipe; tcgen05 PTX is rejected
// by the harness's compute_103 virtual arch).  64 tokens/CTA, 8 warps.
// ===========================================================================

#define CC    384
#define DD    128
#define HIDN  512
#define MT    64
#define NTHR  256
#define EPSV  1e-5f

// smem float offsets (strides 68/132: %32==4 => bank-conflict-free frags)
#define OFF_AB   0        // A chunk  64 x 68
#define OFF_BB   4352     // B chunks 2 x (128 x 68)
#define OFF_VB   21760    // v / lny  64 x 132 (tf32)
#define OFF_YB   30208    // y        64 x 132 (fp32)
#define OFF_GB   38656    // gelu / z 64 x 132
#define OFF_MEAN 47104
#define OFF_RSTD 47168
#define SMEM_FLOATS 47232
#define SMEM_BYTES  (SMEM_FLOATS * 4)

// Pre-transposed tf32 weights, [n][k] row-major (mma row.col B operand)
__device__ float g_WvT[DD * CC];
__device__ float g_WpT[DD * DD];
__device__ float g_W1T[HIDN * DD];
__device__ float g_W2T[DD * HIDN];

__device__ __forceinline__ float to_tf32(float x) {
    uint32_t r; asm("cvt.rna.tf32.f32 %0, %1;" : "=r"(r) : "f"(x));
    return __uint_as_float(r);
}
__device__ __forceinline__ uint32_t smem_u32(const void* p) {
    uint32_t a;
    asm("{ .reg .u64 t; cvta.to.shared.u64 t, %1; cvt.u32.u64 %0, t; }"
        : "=r"(a) : "l"(p));
    return a;
}
__device__ __forceinline__ void cp16(uint32_t dst, const void* src) {
    asm volatile("cp.async.cg.shared.global [%0], [%1], 16;"
                 :: "r"(dst), "l"(src));
}
__device__ __forceinline__ void cp_commit() {
    asm volatile("cp.async.commit_group;" ::: "memory");
}
template<int N> __device__ __forceinline__ void cp_wait() {
    asm volatile("cp.async.wait_group %0;" :: "n"(N) : "memory");
}

__device__ __forceinline__ void mma8(float c[4], const uint32_t a[4],
                                     const uint32_t b[2]) {
    asm volatile(
        "mma.sync.aligned.m16n8k8.row.col.f32.tf32.tf32.f32 "
        "{%0,%1,%2,%3}, {%4,%5,%6,%7}, {%8,%9}, {%0,%1,%2,%3};"
        : "+f"(c[0]), "+f"(c[1]), "+f"(c[2]), "+f"(c[3])
        : "r"(a[0]), "r"(a[1]), "r"(a[2]), "r"(a[3]), "r"(b[0]), "r"(b[1]));
}

// One K=64 chunk: warp (wm,wn) tile 32x32; 8 ksteps x (2 m x 4 n) mma.
__device__ __forceinline__ void mma_chunk(
    const float* __restrict__ As, int lda,   // chunk base (64 rows x 64 k)
    const float* __restrict__ Bs,            // 128 n x 68
    float acc[2][4][4], int wm, int wn, int gid, int tig)
{
    #pragma unroll
    for (int k0 = 0; k0 < 64; k0 += 8) {
        uint32_t a[2][4], b[4][2];
        #pragma unroll
        for (int mi = 0; mi < 2; mi++) {
            const float* ap = As + (wm * 32 + mi * 16 + gid) * lda + k0 + tig;
            a[mi][0] = __float_as_uint(ap[0]);
            a[mi][1] = __float_as_uint(ap[8 * lda]);
            a[mi][2] = __float_as_uint(ap[4]);
            a[mi][3] = __float_as_uint(ap[8 * lda + 4]);
        }
        #pragma unroll
        for (int ni = 0; ni < 4; ni++) {
            const float* bp = Bs + (wn * 32 + ni * 8 + gid) * 68 + k0 + tig;
            b[ni][0] = __float_as_uint(bp[0]);
            b[ni][1] = __float_as_uint(bp[4]);
        }
        #pragma unroll
        for (int mi = 0; mi < 2; mi++)
            #pragma unroll
            for (int ni = 0; ni < 4; ni++)
                mma8(acc[mi][ni], a[mi], b[ni]);
    }
}

// Async-copy one B chunk: rows 0..127, cols kc..kc+63 of Wg[n][ldw]
__device__ __forceinline__ void issueB(float* Bdst, const float* __restrict__ Wg,
                                       int ldw, int kc, int tid)
{
    #pragma unroll
    for (int i = 0; i < 8; i++) {
        int idx = tid + NTHR * i;            // 2048 float4 groups
        int row = idx >> 4;
        int c4  = (idx & 15) << 2;
        cp16(smem_u32(Bdst + row * 68 + c4), Wg + row * ldw + kc + c4);
    }
}

#define ZERO_ACC(A) { _Pragma("unroll") for (int _m=0;_m<2;_m++) \
    _Pragma("unroll") for (int _n=0;_n<4;_n++) \
    _Pragma("unroll") for (int _q=0;_q<4;_q++) (A)[_m][_n][_q] = 0.f; }

// Double-buffered GEMM over NCH K-chunks, A already in smem (tf32).
template<int NCH>
__device__ __forceinline__ void run_gemm(
    float* smem, const float* As, int lda,
    const float* __restrict__ Wg, int ldw, int kbase,
    float acc[2][4][4], int tid, int wm, int wn, int gid, int tig)
{
    float* Bb0 = smem + OFF_BB;
    float* Bb1 = Bb0 + 8704;
    issueB(Bb0, Wg, ldw, kbase, tid); cp_commit();
    #pragma unroll
    for (int c = 0; c < NCH; c++) {
        float* Bcur = (c & 1) ? Bb1 : Bb0;
        if (c + 1 < NCH) {
            issueB((c & 1) ? Bb0 : Bb1, Wg, ldw, kbase + (c + 1) * 64, tid);
            cp_commit();
            cp_wait<1>();
        } else {
            cp_wait<0>();
        }
        __syncthreads();
        mma_chunk(As + c * 64, lda, Bcur, acc, wm, wn, gid, tig);
        __syncthreads();
    }
}

// --------------------------- weight prep kernel ---------------------------
__global__ void prep_kernel(const float* __restrict__ Wkv,
                            const float* __restrict__ Wp,
                            const float* __restrict__ W1,
                            const float* __restrict__ W2) {
    int tid = blockIdx.x * blockDim.x + threadIdx.x;
    int str = gridDim.x * blockDim.x;
    for (int s = tid; s < CC * DD; s += str) {
        int k = s / DD, n = s % DD;
        g_WvT[n * CC + k] = to_tf32(Wkv[k * 256 + 128 + n]);
    }
    for (int s = tid; s < DD * DD; s += str) {
        int k = s / DD, n = s % DD;
        g_WpT[n * DD + k] = to_tf32(Wp[k * DD + n]);
    }
    for (int s = tid; s < DD * HIDN; s += str) {
        int k = s / HIDN, n = s % HIDN;
        g_W1T[n * DD + k] = to_tf32(W1[k * HIDN + n]);
    }
    for (int s = tid; s < HIDN * DD; s += str) {
        int k = s / DD, n = s % DD;
        g_W2T[n * HIDN + k] = to_tf32(W2[k * DD + n]);
    }
}

// ------------------------------ main kernel -------------------------------
extern __shared__ float smem[];

__global__ void __launch_bounds__(NTHR) fused_mma(
    const float* __restrict__ x,
    const float* __restrict__ g1, const float* __restrict__ b1,
    const float* __restrict__ bkv, const float* __restrict__ bp,
    const float* __restrict__ g2, const float* __restrict__ b2,
    const float* __restrict__ bm1, const float* __restrict__ bm2,
    float* __restrict__ out)
{
    float* Ab = smem + OFF_AB;
    float* Vb = smem + OFF_VB;
    float* Yb = smem + OFF_YB;
    float* Gb = smem + OFF_GB;
    float* smean = smem + OFF_MEAN;
    float* srstd = smem + OFF_RSTD;

    const int tid  = threadIdx.x;
    const int lane = tid & 31;
    const int warp = tid >> 5;
    const int wm   = warp >> 2;      // 0..1 (M tile)
    const int wn   = warp & 3;       // 0..3 (N tile)
    const int gid  = lane >> 2;      // 0..7
    const int tig  = lane & 3;       // 0..3
    const long tile0 = (long)blockIdx.x * MT;

    // ---------------- LN(x) stats (8 rows per warp) ----------------
    #pragma unroll 1
    for (int i = 0; i < 8; i++) {
        int row = warp * 8 + i;
        const float* xr = x + (tile0 + row) * CC;
        float s = 0.f, ss = 0.f;
        #pragma unroll
        for (int u = 0; u < 12; u++) {
            float t = xr[lane + 32 * u];
            s += t; ss += t * t;
        }
        #pragma unroll
        for (int o = 16; o > 0; o >>= 1) {
            s  += __shfl_xor_sync(0xffffffffu, s,  o);
            ss += __shfl_xor_sync(0xffffffffu, ss, o);
        }
        if (lane == 0) {
            float m = s * (1.f / 384.f);
            float v = ss * (1.f / 384.f) - m * m;
            smean[row] = m;
            srstd[row] = rsqrtf(v + EPSV);
        }
    }
    __syncthreads();

    // ---------------- v = LN(x) @ WvT  (K=384, 6 chunks) ----------------
    float vacc[2][4][4];
    ZERO_ACC(vacc);
    {
        float* Bb0 = smem + OFF_BB;
        float* Bb1 = Bb0 + 8704;
        issueB(Bb0, g_WvT, CC, 0, tid); cp_commit();
        #pragma unroll 1
        for (int c = 0; c < 6; c++) {
            float* Bcur = (c & 1) ? Bb1 : Bb0;
            if (c < 5) {
                issueB((c & 1) ? Bb0 : Bb1, g_WvT, CC, (c + 1) * 64, tid);
                cp_commit();
            }
            // fill A chunk: normalize x[:, kc..kc+63] -> tf32
            int kc = c * 64;
            #pragma unroll 4
            for (int i = 0; i < 16; i++) {
                int idx = tid + NTHR * i;            // 64 x 64
                int row = idx >> 6, cl = idx & 63;
                int k = kc + cl;
                float t = x[(tile0 + row) * CC + k];
                t = (t - smean[row]) * srstd[row] * g1[k] + b1[k];
                Ab[row * 68 + cl] = to_tf32(t);
            }
            if (c < 5) cp_wait<1>(); else cp_wait<0>();
            __syncthreads();
            mma_chunk(Ab, 68, Bcur, vacc, wm, wn, gid, tig);
            __syncthreads();
        }
    }
    // v epilogue -> Vb (tf32)
    #pragma unroll
    for (int mi = 0; mi < 2; mi++)
        #pragma unroll
        for (int ni = 0; ni < 4; ni++) {
            int r0 = wm * 32 + mi * 16 + gid;
            int cb = wn * 32 + ni * 8 + tig * 2;
            Vb[r0 * 132 + cb]       = to_tf32(vacc[mi][ni][0] + bkv[128 + cb]);
            Vb[r0 * 132 + cb + 1]   = to_tf32(vacc[mi][ni][1] + bkv[129 + cb]);
            Vb[(r0+8) * 132 + cb]   = to_tf32(vacc[mi][ni][2] + bkv[128 + cb]);
            Vb[(r0+8) * 132 + cb+1] = to_tf32(vacc[mi][ni][3] + bkv[129 + cb]);
        }

    // ---------------- y = v @ WpT (K=128) ----------------
    float yacc[2][4][4];
    ZERO_ACC(yacc);
    run_gemm<2>(smem, Vb, 132, g_WpT, DD, 0, yacc, tid, wm, wn, gid, tig);
    #pragma unroll
    for (int mi = 0; mi < 2; mi++)
        #pragma unroll
        for (int ni = 0; ni < 4; ni++) {
            int r0 = wm * 32 + mi * 16 + gid;
            int cb = wn * 32 + ni * 8 + tig * 2;
            Yb[r0 * 132 + cb]       = yacc[mi][ni][0] + bp[cb];
            Yb[r0 * 132 + cb + 1]   = yacc[mi][ni][1] + bp[cb + 1];
            Yb[(r0+8) * 132 + cb]   = yacc[mi][ni][2] + bp[cb];
            Yb[(r0+8) * 132 + cb+1] = yacc[mi][ni][3] + bp[cb + 1];
        }
    __syncthreads();

    // ---------------- lny = LN(y) -> Vb (tf32) ----------------
    #pragma unroll 1
    for (int i = 0; i < 8; i++) {
        int row = warp * 8 + i;
        float vals[4];
        float s = 0.f, ss = 0.f;
        #pragma unroll
        for (int u = 0; u < 4; u++) {
            float t = Yb[row * 132 + lane + 32 * u];
            vals[u] = t; s += t; ss += t * t;
        }
        #pragma unroll
        for (int o = 16; o > 0; o >>= 1) {
            s  += __shfl_xor_sync(0xffffffffu, s,  o);
            ss += __shfl_xor_sync(0xffffffffu, ss, o);
        }
        float m  = s * (1.f / 128.f);
        float vv = ss * (1.f / 128.f) - m * m;
        float rs = rsqrtf(vv + EPSV);
        #pragma unroll
        for (int u = 0; u < 4; u++) {
            int k = lane + 32 * u;
            Vb[row * 132 + k] = to_tf32((vals[u] - m) * rs * g2[k] + b2[k]);
        }
    }
    // (run_gemm's internal pre-mma sync publishes Vb)

    // ---------------- MLP: t = lny@W1T (per 128-col tile), u += gelu@W2T ---
    float uacc[2][4][4];
    ZERO_ACC(uacc);
    #pragma unroll 1
    for (int cc = 0; cc < 4; cc++) {
        float tacc[2][4][4];
        ZERO_ACC(tacc);
        run_gemm<2>(smem, Vb, 132, g_W1T + cc * 128 * DD, DD, 0,
                    tacc, tid, wm, wn, gid, tig);
        // gelu epilogue -> Gb (tf32)
        #pragma unroll
        for (int mi = 0; mi < 2; mi++)
            #pragma unroll
            for (int ni = 0; ni < 4; ni++) {
                int r0 = wm * 32 + mi * 16 + gid;
                int cb = wn * 32 + ni * 8 + tig * 2;
                #pragma unroll
                for (int q = 0; q < 4; q++) {
                    int r = r0 + (q >> 1) * 8;
                    int c = cb + (q & 1);
                    float t = tacc[mi][ni][q] + bm1[cc * 128 + c];
                    float g = 0.5f * t * (1.f + erff(t * 0.70710678118654752f));
                    Gb[r * 132 + c] = to_tf32(g);
                }
            }
        run_gemm<2>(smem, Gb, 132, g_W2T, HIDN, cc * 128,
                    uacc, tid, wm, wn, gid, tig);
    }

    // ---------------- z = y + u + bm2 -> Gb (fp32) -> out ----------------
    #pragma unroll
    for (int mi = 0; mi < 2; mi++)
        #pragma unroll
        for (int ni = 0; ni < 4; ni++) {
            int r0 = wm * 32 + mi * 16 + gid;
            int cb = wn * 32 + ni * 8 + tig * 2;
            #pragma unroll
            for (int q = 0; q < 4; q++) {
                int r = r0 + (q >> 1) * 8;
                int c = cb + (q & 1);
                Gb[r * 132 + c] = Yb[r * 132 + c] + uacc[mi][ni][q] + bm2[c];
            }
        }
    __syncthreads();
    #pragma unroll
    for (int i = 0; i < 8; i++) {
        int idx = tid + NTHR * i;            // 2048 float4
        int row = idx >> 5;
        int c   = (idx & 31) * 4;
        float4 v4 = *(const float4*)(Gb + row * 132 + c);
        *(float4*)(out + (tile0 + row) * DD + c) = v4;
    }
}

// ------------------------------ launcher ----------------------------------
extern "C" void kernel_launch(void* const* d_in, const int* in_sizes, int n_in,
                              void* d_out, int out_size)
{
    const float* x   = (const float*)d_in[0];
    const float* g1  = (const float*)d_in[1];
    const float* b1  = (const float*)d_in[2];
    // d_in[3]=Wq, d_in[4]=bq, d_in[7]=rpb : dead
    const float* Wkv = (const float*)d_in[5];
    const float* bkv = (const float*)d_in[6];
    const float* Wp  = (const float*)d_in[8];
    const float* bp  = (const float*)d_in[9];
    const float* g2  = (const float*)d_in[10];
    const float* b2  = (const float*)d_in[11];
    const float* W1  = (const float*)d_in[12];
    const float* bm1 = (const float*)d_in[13];
    const float* W2  = (const float*)d_in[14];
    const float* bm2 = (const float*)d_in[15];
    float* out = (float*)d_out;

    cudaFuncSetAttribute(fused_mma,
                         cudaFuncAttributeMaxDynamicSharedMemorySize,
                         SMEM_BYTES);

    prep_kernel<<<192, 256>>>(Wkv, Wp, W1, W2);

    const int tokens = in_sizes[0] / CC;   // 65536
    const int grid   = tokens / MT;        // 1024
    fused_mma<<<grid, NTHR, SMEM_BYTES>>>(
        x, g1, b1, bkv, bp, g2, b2, bm1, bm2, out);
}

// round 4
// speedup vs baseline: 6.7473x; 1.8600x over previous
#include <cuda_runtime.h>
#include <cuda_fp16.h>
#include <math.h>
#include <stdint.h>

// ===========================================================================
// Live math (softmax over size-1 axis == 1 kills q/Wq/bq/rpb/k-half of Wkv):
//   h = LN(x;g1,b1); v = h@Wv+bv; y = v@Wp+bp;
//   z = y + gelu(LN(y;g2,b2)@W1+bm1)@W2 + bm2
// GEMMs on mma.sync m16n8k16 fp16 (fp32 accum).  64 tokens/CTA, 8 warps,
// 2 CTAs/SM (smem 103.5KB, 128 regs).
// ===========================================================================

#define CC    384
#define DD    128
#define HIDN  512
#define MT    64
#define NTHR  256
#define EPSV  1e-5f

// fp16 row strides: 72 (K=64 chunks), 136 (128-col bufs) — stride%64==8
// gives conflict-free 8x4 fragment footprints. fp32 stride 132 (%32==4).
#define BSTR  72
#define VSTR  136
#define YSTR  132

// smem byte offsets
#define OFF_BB   0                    // 2 x (128 x 72) fp16 = 36864
#define OFF_VB   36864                // v / lny : 64 x 136 fp16 = 17408
#define OFF_GB   54272                // gelu    : 64 x 136 fp16 = 17408
                                      //   (A-chunk 64x72 fp16 aliases here)
#define OFF_YB   71680                // y / z   : 64 x 132 fp32 = 33792
#define OFF_MEAN 105472
#define OFF_RSTD 105728
#define SMEM_BYTES 105984

// Pre-transposed fp16 weights, [n][k] row-major (mma row.col B operand)
__device__ __half g_WvT[DD * CC];
__device__ __half g_WpT[DD * DD];
__device__ __half g_W1T[HIDN * DD];
__device__ __half g_W2T[DD * HIDN];

__device__ __forceinline__ uint32_t smem_u32(const void* p) {
    uint32_t a;
    asm("{ .reg .u64 t; cvta.to.shared.u64 t, %1; cvt.u32.u64 %0, t; }"
        : "=r"(a) : "l"(p));
    return a;
}
__device__ __forceinline__ void cp16(uint32_t dst, const void* src) {
    asm volatile("cp.async.cg.shared.global [%0], [%1], 16;"
                 :: "r"(dst), "l"(src));
}
__device__ __forceinline__ void cp_commit() {
    asm volatile("cp.async.commit_group;" ::: "memory");
}
template<int N> __device__ __forceinline__ void cp_wait() {
    asm volatile("cp.async.wait_group %0;" :: "n"(N) : "memory");
}

__device__ __forceinline__ void mma16(float c[4], const uint32_t a[4],
                                      const uint32_t b[2]) {
    asm volatile(
        "mma.sync.aligned.m16n8k16.row.col.f32.f16.f16.f32 "
        "{%0,%1,%2,%3}, {%4,%5,%6,%7}, {%8,%9}, {%0,%1,%2,%3};"
        : "+f"(c[0]), "+f"(c[1]), "+f"(c[2]), "+f"(c[3])
        : "r"(a[0]), "r"(a[1]), "r"(a[2]), "r"(a[3]), "r"(b[0]), "r"(b[1]));
}

// One K=64 chunk: warp (wm,wn) tile 32x32; 4 ksteps x (2 m x 4 n) mma.
__device__ __forceinline__ void mma_chunk(
    const __half* __restrict__ As, int lda,   // 64 rows x 64 k (fp16)
    const __half* __restrict__ Bs,            // 128 n x BSTR
    float acc[2][4][4], int wm, int wn, int gid, int tig)
{
    #pragma unroll
    for (int k0 = 0; k0 < 64; k0 += 16) {
        uint32_t a[2][4], b[4][2];
        #pragma unroll
        for (int mi = 0; mi < 2; mi++) {
            const __half* ap = As + (wm * 32 + mi * 16 + gid) * lda + k0 + 2 * tig;
            a[mi][0] = *(const uint32_t*)(ap);
            a[mi][1] = *(const uint32_t*)(ap + 8 * lda);
            a[mi][2] = *(const uint32_t*)(ap + 8);
            a[mi][3] = *(const uint32_t*)(ap + 8 * lda + 8);
        }
        #pragma unroll
        for (int ni = 0; ni < 4; ni++) {
            const __half* bp = Bs + (wn * 32 + ni * 8 + gid) * BSTR + k0 + 2 * tig;
            b[ni][0] = *(const uint32_t*)(bp);
            b[ni][1] = *(const uint32_t*)(bp + 8);
        }
        #pragma unroll
        for (int mi = 0; mi < 2; mi++)
            #pragma unroll
            for (int ni = 0; ni < 4; ni++)
                mma16(acc[mi][ni], a[mi], b[ni]);
    }
}

// Async-copy one B chunk: rows 0..127, cols kc..kc+63 of Wg[n][ldw] (fp16)
__device__ __forceinline__ void issueB(__half* Bdst, const __half* __restrict__ Wg,
                                       int ldw, int kc, int tid)
{
    #pragma unroll
    for (int i = 0; i < 4; i++) {
        int idx = tid + NTHR * i;            // 1024 groups of 8 halves
        int row = idx >> 3;
        int g8  = (idx & 7) << 3;
        cp16(smem_u32(Bdst + row * BSTR + g8), Wg + row * ldw + kc + g8);
    }
}

#define ZERO_ACC(A) { _Pragma("unroll") for (int _m=0;_m<2;_m++) \
    _Pragma("unroll") for (int _n=0;_n<4;_n++) \
    _Pragma("unroll") for (int _q=0;_q<4;_q++) (A)[_m][_n][_q] = 0.f; }

// Double-buffered GEMM over NCH K=64 chunks, A already in smem (fp16).
template<int NCH>
__device__ __forceinline__ void run_gemm(
    __half* Bb, const __half* As, int lda,
    const __half* __restrict__ Wg, int ldw, int kbase,
    float acc[2][4][4], int tid, int wm, int wn, int gid, int tig)
{
    __half* Bb0 = Bb;
    __half* Bb1 = Bb + 128 * BSTR;
    issueB(Bb0, Wg, ldw, kbase, tid); cp_commit();
    #pragma unroll
    for (int c = 0; c < NCH; c++) {
        __half* Bcur = (c & 1) ? Bb1 : Bb0;
        if (c + 1 < NCH) {
            issueB((c & 1) ? Bb0 : Bb1, Wg, ldw, kbase + (c + 1) * 64, tid);
            cp_commit();
            cp_wait<1>();
        } else {
            cp_wait<0>();
        }
        __syncthreads();
        mma_chunk(As + c * 64, lda, Bcur, acc, wm, wn, gid, tig);
        __syncthreads();
    }
}

// --------------------------- weight prep kernel ---------------------------
__global__ void prep_kernel(const float* __restrict__ Wkv,
                            const float* __restrict__ Wp,
                            const float* __restrict__ W1,
                            const float* __restrict__ W2) {
    int tid = blockIdx.x * blockDim.x + threadIdx.x;
    int str = gridDim.x * blockDim.x;
    for (int s = tid; s < CC * DD; s += str) {
        int k = s / DD, n = s % DD;
        g_WvT[n * CC + k] = __float2half_rn(Wkv[k * 256 + 128 + n]);
    }
    for (int s = tid; s < DD * DD; s += str) {
        int k = s / DD, n = s % DD;
        g_WpT[n * DD + k] = __float2half_rn(Wp[k * DD + n]);
    }
    for (int s = tid; s < DD * HIDN; s += str) {
        int k = s / HIDN, n = s % HIDN;
        g_W1T[n * DD + k] = __float2half_rn(W1[k * HIDN + n]);
    }
    for (int s = tid; s < HIDN * DD; s += str) {
        int k = s / DD, n = s % DD;
        g_W2T[n * HIDN + k] = __float2half_rn(W2[k * DD + n]);
    }
}

// ------------------------------ main kernel -------------------------------
extern __shared__ char smem_raw[];

__global__ void __launch_bounds__(NTHR, 2) fused_mma(
    const float* __restrict__ x,
    const float* __restrict__ g1, const float* __restrict__ b1,
    const float* __restrict__ bkv, const float* __restrict__ bp,
    const float* __restrict__ g2, const float* __restrict__ b2,
    const float* __restrict__ bm1, const float* __restrict__ bm2,
    float* __restrict__ out)
{
    __half* Bb = (__half*)(smem_raw + OFF_BB);
    __half* Vb = (__half*)(smem_raw + OFF_VB);
    __half* Gb = (__half*)(smem_raw + OFF_GB);
    __half* Ab = (__half*)(smem_raw + OFF_GB);   // alias: stage-2 only
    float*  Yb = (float*)(smem_raw + OFF_YB);
    float* smean = (float*)(smem_raw + OFF_MEAN);
    float* srstd = (float*)(smem_raw + OFF_RSTD);

    const int tid  = threadIdx.x;
    const int lane = tid & 31;
    const int warp = tid >> 5;
    const int wm   = warp >> 2;      // 0..1 (M tile)
    const int wn   = warp & 3;       // 0..3 (N tile)
    const int gid  = lane >> 2;      // 0..7
    const int tig  = lane & 3;       // 0..3
    const long tile0 = (long)blockIdx.x * MT;

    // ---------------- LN(x) stats (8 rows per warp) ----------------
    #pragma unroll 1
    for (int i = 0; i < 8; i++) {
        int row = warp * 8 + i;
        const float* xr = x + (tile0 + row) * CC;
        float s = 0.f, ss = 0.f;
        #pragma unroll
        for (int u = 0; u < 12; u++) {
            float t = xr[lane + 32 * u];
            s += t; ss += t * t;
        }
        #pragma unroll
        for (int o = 16; o > 0; o >>= 1) {
            s  += __shfl_xor_sync(0xffffffffu, s,  o);
            ss += __shfl_xor_sync(0xffffffffu, ss, o);
        }
        if (lane == 0) {
            float m = s * (1.f / 384.f);
            float v = ss * (1.f / 384.f) - m * m;
            smean[row] = m;
            srstd[row] = rsqrtf(v + EPSV);
        }
    }
    __syncthreads();

    // ---------------- v = LN(x) @ WvT  (K=384, 6 chunks) ----------------
    float vacc[2][4][4];
    ZERO_ACC(vacc);
    {
        __half* Bb0 = Bb;
        __half* Bb1 = Bb + 128 * BSTR;
        issueB(Bb0, g_WvT, CC, 0, tid); cp_commit();
        #pragma unroll 1
        for (int c = 0; c < 6; c++) {
            __half* Bcur = (c & 1) ? Bb1 : Bb0;
            if (c < 5) {
                issueB((c & 1) ? Bb0 : Bb1, g_WvT, CC, (c + 1) * 64, tid);
                cp_commit();
            }
            // fill A chunk: normalize x[:, kc..kc+63] -> fp16
            int kc = c * 64;
            #pragma unroll 4
            for (int i = 0; i < 16; i++) {
                int idx = tid + NTHR * i;            // 64 x 64
                int row = idx >> 6, cl = idx & 63;
                int k = kc + cl;
                float t = x[(tile0 + row) * CC + k];
                t = (t - smean[row]) * srstd[row] * g1[k] + b1[k];
                Ab[row * BSTR + cl] = __float2half_rn(t);
            }
            if (c < 5) cp_wait<1>(); else cp_wait<0>();
            __syncthreads();
            mma_chunk(Ab, BSTR, Bcur, vacc, wm, wn, gid, tig);
            __syncthreads();
        }
    }
    // v epilogue -> Vb (fp16)
    #pragma unroll
    for (int mi = 0; mi < 2; mi++)
        #pragma unroll
        for (int ni = 0; ni < 4; ni++) {
            int r0 = wm * 32 + mi * 16 + gid;
            int cb = wn * 32 + ni * 8 + tig * 2;
            float b0 = bkv[128 + cb], b1v = bkv[129 + cb];
            *(__half2*)(Vb + r0 * VSTR + cb) =
                __floats2half2_rn(vacc[mi][ni][0] + b0, vacc[mi][ni][1] + b1v);
            *(__half2*)(Vb + (r0 + 8) * VSTR + cb) =
                __floats2half2_rn(vacc[mi][ni][2] + b0, vacc[mi][ni][3] + b1v);
        }

    // ---------------- y = v @ WpT (K=128) ----------------
    float yacc[2][4][4];
    ZERO_ACC(yacc);
    run_gemm<2>(Bb, Vb, VSTR, g_WpT, DD, 0, yacc, tid, wm, wn, gid, tig);
    #pragma unroll
    for (int mi = 0; mi < 2; mi++)
        #pragma unroll
        for (int ni = 0; ni < 4; ni++) {
            int r0 = wm * 32 + mi * 16 + gid;
            int cb = wn * 32 + ni * 8 + tig * 2;
            Yb[r0 * YSTR + cb]         = yacc[mi][ni][0] + bp[cb];
            Yb[r0 * YSTR + cb + 1]     = yacc[mi][ni][1] + bp[cb + 1];
            Yb[(r0 + 8) * YSTR + cb]   = yacc[mi][ni][2] + bp[cb];
            Yb[(r0 + 8) * YSTR + cb+1] = yacc[mi][ni][3] + bp[cb + 1];
        }
    __syncthreads();

    // ---------------- lny = LN(y) -> Vb (fp16) ----------------
    #pragma unroll 1
    for (int i = 0; i < 8; i++) {
        int row = warp * 8 + i;
        float vals[4];
        float s = 0.f, ss = 0.f;
        #pragma unroll
        for (int u = 0; u < 4; u++) {
            float t = Yb[row * YSTR + lane + 32 * u];
            vals[u] = t; s += t; ss += t * t;
        }
        #pragma unroll
        for (int o = 16; o > 0; o >>= 1) {
            s  += __shfl_xor_sync(0xffffffffu, s,  o);
            ss += __shfl_xor_sync(0xffffffffu, ss, o);
        }
        float m  = s * (1.f / 128.f);
        float vv = ss * (1.f / 128.f) - m * m;
        float rs = rsqrtf(vv + EPSV);
        #pragma unroll
        for (int u = 0; u < 4; u++) {
            int k = lane + 32 * u;
            Vb[row * VSTR + k] =
                __float2half_rn((vals[u] - m) * rs * g2[k] + b2[k]);
        }
    }
    // (run_gemm's internal pre-mma sync publishes Vb)

    // ---------------- MLP: t = lny@W1T (per 128-col tile), u += gelu@W2T ---
    float uacc[2][4][4];
    ZERO_ACC(uacc);
    #pragma unroll 1
    for (int cc = 0; cc < 4; cc++) {
        float tacc[2][4][4];
        ZERO_ACC(tacc);
        run_gemm<2>(Bb, Vb, VSTR, g_W1T + cc * 128 * DD, DD, 0,
                    tacc, tid, wm, wn, gid, tig);
        // gelu epilogue -> Gb (fp16)
        #pragma unroll
        for (int mi = 0; mi < 2; mi++)
            #pragma unroll
            for (int ni = 0; ni < 4; ni++) {
                int r0 = wm * 32 + mi * 16 + gid;
                int cb = wn * 32 + ni * 8 + tig * 2;
                float bb0 = bm1[cc * 128 + cb], bb1 = bm1[cc * 128 + cb + 1];
                float t0 = tacc[mi][ni][0] + bb0;
                float t1 = tacc[mi][ni][1] + bb1;
                float t2 = tacc[mi][ni][2] + bb0;
                float t3 = tacc[mi][ni][3] + bb1;
                float s2 = 0.70710678118654752f;
                *(__half2*)(Gb + r0 * VSTR + cb) = __floats2half2_rn(
                    0.5f * t0 * (1.f + erff(t0 * s2)),
                    0.5f * t1 * (1.f + erff(t1 * s2)));
                *(__half2*)(Gb + (r0 + 8) * VSTR + cb) = __floats2half2_rn(
                    0.5f * t2 * (1.f + erff(t2 * s2)),
                    0.5f * t3 * (1.f + erff(t3 * s2)));
            }
        run_gemm<2>(Bb, Gb, VSTR, g_W2T, HIDN, cc * 128,
                    uacc, tid, wm, wn, gid, tig);
    }

    // ---------------- z = y + u + bm2 -> Yb (in place) -> out ----------------
    #pragma unroll
    for (int mi = 0; mi < 2; mi++)
        #pragma unroll
        for (int ni = 0; ni < 4; ni++) {
            int r0 = wm * 32 + mi * 16 + gid;
            int cb = wn * 32 + ni * 8 + tig * 2;
            Yb[r0 * YSTR + cb]         += uacc[mi][ni][0] + bm2[cb];
            Yb[r0 * YSTR + cb + 1]     += uacc[mi][ni][1] + bm2[cb + 1];
            Yb[(r0 + 8) * YSTR + cb]   += uacc[mi][ni][2] + bm2[cb];
            Yb[(r0 + 8) * YSTR + cb+1] += uacc[mi][ni][3] + bm2[cb + 1];
        }
    __syncthreads();
    #pragma unroll
    for (int i = 0; i < 8; i++) {
        int idx = tid + NTHR * i;            // 2048 float4
        int row = idx >> 5;
        int c   = (idx & 31) * 4;
        float4 v4 = *(const float4*)(Yb + row * YSTR + c);
        *(float4*)(out + (tile0 + row) * DD + c) = v4;
    }
}

// ------------------------------ launcher ----------------------------------
extern "C" void kernel_launch(void* const* d_in, const int* in_sizes, int n_in,
                              void* d_out, int out_size)
{
    const float* x   = (const float*)d_in[0];
    const float* g1  = (const float*)d_in[1];
    const float* b1  = (const float*)d_in[2];
    // d_in[3]=Wq, d_in[4]=bq, d_in[7]=rpb : dead
    const float* Wkv = (const float*)d_in[5];
    const float* bkv = (const float*)d_in[6];
    const float* Wp  = (const float*)d_in[8];
    const float* bp  = (const float*)d_in[9];
    const float* g2  = (const float*)d_in[10];
    const float* b2  = (const float*)d_in[11];
    const float* W1  = (const float*)d_in[12];
    const float* bm1 = (const float*)d_in[13];
    const float* W2  = (const float*)d_in[14];
    const float* bm2 = (const float*)d_in[15];
    float* out = (float*)d_out;

    cudaFuncSetAttribute(fused_mma,
                         cudaFuncAttributeMaxDynamicSharedMemorySize,
                         SMEM_BYTES);

    prep_kernel<<<192, 256>>>(Wkv, Wp, W1, W2);

    const int tokens = in_sizes[0] / CC;   // 65536
    const int grid   = tokens / MT;        // 1024
    fused_mma<<<grid, NTHR, SMEM_BYTES>>>(
        x, g1, b1, bkv, bp, g2, b2, bm1, bm2, out);
}

// round 5
// speedup vs baseline: 7.6152x; 1.1286x over previous
#include <cuda_runtime.h>
#include <cuda_fp16.h>
#include <math.h>
#include <stdint.h>

// ===========================================================================
// Live math (softmax over size-1 axis == 1 kills q/Wq/bq/rpb/k-half of Wkv):
//   h = LN(x;g1,b1); v = h@Wv+bv; y = v@Wp+bp;
//   z = y + gelu(LN(y;g2,b2)@W1+bm1)@W2 + bm2
// GEMMs on mma.sync m16n8k16 fp16 (fp32 accum), ldmatrix fragment loads,
// cross-phase cp.async B prefetch.  64 tokens/CTA, 8 warps, 2 CTAs/SM.
// ===========================================================================

#define CC    384
#define DD    128
#define HIDN  512
#define MT    64
#define NTHR  256
#define EPSV  1e-5f

// fp16 row strides: 72 (K=64 chunks), 136 (128-col bufs): stride*2B mod 128B
// steps 16B per row -> ldmatrix conflict-free. fp32 stride 132 (%32==4).
#define BSTR  72
#define VSTR  136
#define YSTR  132

// smem byte offsets
#define OFF_BB   0                    // 2 x (128 x 72) fp16 = 36864
#define OFF_VB   36864                // v / lny : 64 x 136 fp16 = 17408
#define OFF_GB   54272                // gelu    : 64 x 136 fp16 = 17408
                                      //   (A-chunk 64x72 fp16 aliases here)
#define OFF_YB   71680                // y / z   : 64 x 132 fp32 = 33792
#define OFF_MEAN 105472
#define OFF_RSTD 105728
#define SMEM_BYTES 105984

// Pre-transposed fp16 weights, [n][k] row-major (mma row.col B operand)
__device__ __half g_WvT[DD * CC];
__device__ __half g_WpT[DD * DD];
__device__ __half g_W1T[HIDN * DD];
__device__ __half g_W2T[DD * HIDN];

__device__ __forceinline__ uint32_t smem_u32(const void* p) {
    uint32_t a;
    asm("{ .reg .u64 t; cvta.to.shared.u64 t, %1; cvt.u32.u64 %0, t; }"
        : "=r"(a) : "l"(p));
    return a;
}
__device__ __forceinline__ void cp16(uint32_t dst, const void* src) {
    asm volatile("cp.async.cg.shared.global [%0], [%1], 16;"
                 :: "r"(dst), "l"(src));
}
__device__ __forceinline__ void cp_commit() {
    asm volatile("cp.async.commit_group;" ::: "memory");
}
template<int N> __device__ __forceinline__ void cp_wait() {
    asm volatile("cp.async.wait_group %0;" :: "n"(N) : "memory");
}
__device__ __forceinline__ void ldsm4(uint32_t r[4], uint32_t addr) {
    asm volatile("ldmatrix.sync.aligned.m8n8.x4.shared.b16 {%0,%1,%2,%3}, [%4];"
                 : "=r"(r[0]), "=r"(r[1]), "=r"(r[2]), "=r"(r[3]) : "r"(addr));
}
__device__ __forceinline__ void mma16(float c[4],
    uint32_t a0, uint32_t a1, uint32_t a2, uint32_t a3,
    uint32_t b0, uint32_t b1) {
    asm volatile(
        "mma.sync.aligned.m16n8k16.row.col.f32.f16.f16.f32 "
        "{%0,%1,%2,%3}, {%4,%5,%6,%7}, {%8,%9}, {%0,%1,%2,%3};"
        : "+f"(c[0]), "+f"(c[1]), "+f"(c[2]), "+f"(c[3])
        : "r"(a0), "r"(a1), "r"(a2), "r"(a3), "r"(b0), "r"(b1));
}

// One K=64 chunk: warp (wm,wn) tile 32x32; ldmatrix frags, 4 ksteps x 8 mma.
__device__ __forceinline__ void mma_chunk(
    const __half* __restrict__ As, int lda,   // 64 rows x 64 k (fp16)
    const __half* __restrict__ Bs,            // 128 n x BSTR
    float acc[2][4][4], int wm, int wn, int lane)
{
    const int lrow = lane & 15;
    const int lcol = (lane >> 4) << 3;
    uint32_t aA0 = smem_u32(As + (wm * 32 +      lrow) * lda + lcol);
    uint32_t aA1 = smem_u32(As + (wm * 32 + 16 + lrow) * lda + lcol);
    uint32_t aB0 = smem_u32(Bs + (wn * 32 +      lrow) * BSTR + lcol);
    uint32_t aB1 = smem_u32(Bs + (wn * 32 + 16 + lrow) * BSTR + lcol);
    #pragma unroll
    for (int k0 = 0; k0 < 64; k0 += 16) {
        uint32_t a0[4], a1[4], b0[4], b1[4];
        ldsm4(a0, aA0 + k0 * 2);
        ldsm4(a1, aA1 + k0 * 2);
        ldsm4(b0, aB0 + k0 * 2);
        ldsm4(b1, aB1 + k0 * 2);
        // b0: n tiles (+0,+8); b1: (+16,+24)
        mma16(acc[0][0], a0[0],a0[1],a0[2],a0[3], b0[0], b0[2]);
        mma16(acc[0][1], a0[0],a0[1],a0[2],a0[3], b0[1], b0[3]);
        mma16(acc[0][2], a0[0],a0[1],a0[2],a0[3], b1[0], b1[2]);
        mma16(acc[0][3], a0[0],a0[1],a0[2],a0[3], b1[1], b1[3]);
        mma16(acc[1][0], a1[0],a1[1],a1[2],a1[3], b0[0], b0[2]);
        mma16(acc[1][1], a1[0],a1[1],a1[2],a1[3], b0[1], b0[3]);
        mma16(acc[1][2], a1[0],a1[1],a1[2],a1[3], b1[0], b1[2]);
        mma16(acc[1][3], a1[0],a1[1],a1[2],a1[3], b1[1], b1[3]);
    }
}

// Async-copy one B chunk: rows 0..127, cols kc..kc+63 of Wg[n][ldw] (fp16)
__device__ __forceinline__ void issueB(__half* Bdst, const __half* __restrict__ Wg,
                                       int ldw, int kc, int tid)
{
    #pragma unroll
    for (int i = 0; i < 4; i++) {
        int idx = tid + NTHR * i;            // 1024 groups of 8 halves
        int row = idx >> 3;
        int g8  = (idx & 7) << 3;
        cp16(smem_u32(Bdst + row * BSTR + g8), Wg + row * ldw + kc + g8);
    }
}

#define ZERO_ACC(A) { _Pragma("unroll") for (int _m=0;_m<2;_m++) \
    _Pragma("unroll") for (int _n=0;_n<4;_n++) \
    _Pragma("unroll") for (int _q=0;_q<4;_q++) (A)[_m][_n][_q] = 0.f; }

// Double-buffered GEMM over NCH K=64 chunks. Chunk0 cp.async into Bb0 was
// already issued+committed by the caller (prefetch, overlapped w/ epilogue).
template<int NCH>
__device__ __forceinline__ void run_gemm(
    __half* Bb, const __half* As, int lda,
    const __half* __restrict__ Wg, int ldw, int kbase,
    float acc[2][4][4], int tid, int wm, int wn, int lane)
{
    __half* Bb0 = Bb;
    __half* Bb1 = Bb + 128 * BSTR;
    #pragma unroll
    for (int c = 0; c < NCH; c++) {
        __half* Bcur = (c & 1) ? Bb1 : Bb0;
        if (c + 1 < NCH) {
            issueB((c & 1) ? Bb0 : Bb1, Wg, ldw, kbase + (c + 1) * 64, tid);
            cp_commit();
            cp_wait<1>();
        } else {
            cp_wait<0>();
        }
        __syncthreads();
        mma_chunk(As + c * 64, lda, Bcur, acc, wm, wn, lane);
        __syncthreads();
    }
}

// --------------------------- weight prep kernel ---------------------------
__global__ void prep_kernel(const float* __restrict__ Wkv,
                            const float* __restrict__ Wp,
                            const float* __restrict__ W1,
                            const float* __restrict__ W2) {
    int tid = blockIdx.x * blockDim.x + threadIdx.x;
    int str = gridDim.x * blockDim.x;
    for (int s = tid; s < CC * DD; s += str) {
        int k = s / DD, n = s % DD;
        g_WvT[n * CC + k] = __float2half_rn(Wkv[k * 256 + 128 + n]);
    }
    for (int s = tid; s < DD * DD; s += str) {
        int k = s / DD, n = s % DD;
        g_WpT[n * DD + k] = __float2half_rn(Wp[k * DD + n]);
    }
    for (int s = tid; s < DD * HIDN; s += str) {
        int k = s / HIDN, n = s % HIDN;
        g_W1T[n * DD + k] = __float2half_rn(W1[k * HIDN + n]);
    }
    for (int s = tid; s < HIDN * DD; s += str) {
        int k = s / DD, n = s % DD;
        g_W2T[n * HIDN + k] = __float2half_rn(W2[k * DD + n]);
    }
}

// ------------------------------ main kernel -------------------------------
extern __shared__ char smem_raw[];

__global__ void __launch_bounds__(NTHR, 2) fused_mma(
    const float* __restrict__ x,
    const float* __restrict__ g1, const float* __restrict__ b1,
    const float* __restrict__ bkv, const float* __restrict__ bp,
    const float* __restrict__ g2, const float* __restrict__ b2,
    const float* __restrict__ bm1, const float* __restrict__ bm2,
    float* __restrict__ out)
{
    __half* Bb = (__half*)(smem_raw + OFF_BB);
    __half* Vb = (__half*)(smem_raw + OFF_VB);
    __half* Gb = (__half*)(smem_raw + OFF_GB);
    __half* Ab = (__half*)(smem_raw + OFF_GB);   // alias: stage-2 only
    float*  Yb = (float*)(smem_raw + OFF_YB);
    float* smean = (float*)(smem_raw + OFF_MEAN);
    float* srstd = (float*)(smem_raw + OFF_RSTD);
    __half* Bb0 = Bb;
    __half* Bb1 = Bb + 128 * BSTR;

    const int tid  = threadIdx.x;
    const int lane = tid & 31;
    const int warp = tid >> 5;
    const int wm   = warp >> 2;      // 0..1 (M tile)
    const int wn   = warp & 3;       // 0..3 (N tile)
    const int gid  = lane >> 2;      // 0..7
    const int tig  = lane & 3;       // 0..3
    const long tile0 = (long)blockIdx.x * MT;

    // Prefetch first Wv B-chunk: hides under LN stats.
    issueB(Bb0, g_WvT, CC, 0, tid); cp_commit();

    // ---------------- LN(x) stats (8 rows per warp) ----------------
    #pragma unroll 1
    for (int i = 0; i < 8; i++) {
        int row = warp * 8 + i;
        const float* xr = x + (tile0 + row) * CC;
        float s = 0.f, ss = 0.f;
        #pragma unroll
        for (int u = 0; u < 12; u++) {
            float t = xr[lane + 32 * u];
            s += t; ss += t * t;
        }
        #pragma unroll
        for (int o = 16; o > 0; o >>= 1) {
            s  += __shfl_xor_sync(0xffffffffu, s,  o);
            ss += __shfl_xor_sync(0xffffffffu, ss, o);
        }
        if (lane == 0) {
            float m = s * (1.f / 384.f);
            float v = ss * (1.f / 384.f) - m * m;
            smean[row] = m;
            srstd[row] = rsqrtf(v + EPSV);
        }
    }
    __syncthreads();

    // ---------------- v = LN(x) @ WvT  (K=384, 6 chunks) ----------------
    float vacc[2][4][4];
    ZERO_ACC(vacc);
    #pragma unroll 1
    for (int c = 0; c < 6; c++) {
        __half* Bcur = (c & 1) ? Bb1 : Bb0;
        if (c < 5) {
            issueB((c & 1) ? Bb0 : Bb1, g_WvT, CC, (c + 1) * 64, tid);
            cp_commit();
        }
        // fill A chunk: normalize x[:, kc..kc+63] -> fp16 (half2 stores)
        int kc = c * 64;
        #pragma unroll 8
        for (int i = 0; i < 8; i++) {
            int idx = tid + NTHR * i;            // 64 rows x 32 col-pairs
            int row = idx >> 5, c2 = (idx & 31) * 2;
            int k = kc + c2;
            float2 xx = *(const float2*)(x + (tile0 + row) * CC + k);
            float m = smean[row], rs = srstd[row];
            float t0 = (xx.x - m) * rs * g1[k]     + b1[k];
            float t1 = (xx.y - m) * rs * g1[k + 1] + b1[k + 1];
            *(__half2*)(Ab + row * BSTR + c2) = __floats2half2_rn(t0, t1);
        }
        if (c < 5) cp_wait<1>(); else cp_wait<0>();
        __syncthreads();
        mma_chunk(Ab, BSTR, Bcur, vacc, wm, wn, lane);
        __syncthreads();
    }

    // Prefetch Wp chunk0: hides under v epilogue.
    issueB(Bb0, g_WpT, DD, 0, tid); cp_commit();

    // v epilogue -> Vb (fp16)
    #pragma unroll
    for (int mi = 0; mi < 2; mi++)
        #pragma unroll
        for (int ni = 0; ni < 4; ni++) {
            int r0 = wm * 32 + mi * 16 + gid;
            int cb = wn * 32 + ni * 8 + tig * 2;
            float b0 = bkv[128 + cb], b1v = bkv[129 + cb];
            *(__half2*)(Vb + r0 * VSTR + cb) =
                __floats2half2_rn(vacc[mi][ni][0] + b0, vacc[mi][ni][1] + b1v);
            *(__half2*)(Vb + (r0 + 8) * VSTR + cb) =
                __floats2half2_rn(vacc[mi][ni][2] + b0, vacc[mi][ni][3] + b1v);
        }

    // ---------------- y = v @ WpT (K=128) ----------------
    float yacc[2][4][4];
    ZERO_ACC(yacc);
    run_gemm<2>(Bb, Vb, VSTR, g_WpT, DD, 0, yacc, tid, wm, wn, lane);

    // Prefetch W1 (cc=0) chunk0: hides under y epilogue + LN(y).
    issueB(Bb0, g_W1T, DD, 0, tid); cp_commit();

    #pragma unroll
    for (int mi = 0; mi < 2; mi++)
        #pragma unroll
        for (int ni = 0; ni < 4; ni++) {
            int r0 = wm * 32 + mi * 16 + gid;
            int cb = wn * 32 + ni * 8 + tig * 2;
            Yb[r0 * YSTR + cb]         = yacc[mi][ni][0] + bp[cb];
            Yb[r0 * YSTR + cb + 1]     = yacc[mi][ni][1] + bp[cb + 1];
            Yb[(r0 + 8) * YSTR + cb]   = yacc[mi][ni][2] + bp[cb];
            Yb[(r0 + 8) * YSTR + cb+1] = yacc[mi][ni][3] + bp[cb + 1];
        }
    __syncthreads();

    // ---------------- lny = LN(y) -> Vb (fp16) ----------------
    #pragma unroll 1
    for (int i = 0; i < 8; i++) {
        int row = warp * 8 + i;
        float vals[4];
        float s = 0.f, ss = 0.f;
        #pragma unroll
        for (int u = 0; u < 4; u++) {
            float t = Yb[row * YSTR + lane + 32 * u];
            vals[u] = t; s += t; ss += t * t;
        }
        #pragma unroll
        for (int o = 16; o > 0; o >>= 1) {
            s  += __shfl_xor_sync(0xffffffffu, s,  o);
            ss += __shfl_xor_sync(0xffffffffu, ss, o);
        }
        float m  = s * (1.f / 128.f);
        float vv = ss * (1.f / 128.f) - m * m;
        float rs = rsqrtf(vv + EPSV);
        #pragma unroll
        for (int u = 0; u < 4; u++) {
            int k = lane + 32 * u;
            Vb[row * VSTR + k] =
                __float2half_rn((vals[u] - m) * rs * g2[k] + b2[k]);
        }
    }
    // (run_gemm's internal pre-mma sync publishes Vb)

    // ---------------- MLP: t = lny@W1T (per 128-col tile), u += gelu@W2T ---
    float uacc[2][4][4];
    ZERO_ACC(uacc);
    #pragma unroll 1
    for (int cc = 0; cc < 4; cc++) {
        float tacc[2][4][4];
        ZERO_ACC(tacc);
        run_gemm<2>(Bb, Vb, VSTR, g_W1T + cc * 128 * DD, DD, 0,
                    tacc, tid, wm, wn, lane);

        // Prefetch W2 (cc) chunk0: hides under gelu epilogue.
        issueB(Bb0, g_W2T, HIDN, cc * 128, tid); cp_commit();

        // gelu epilogue -> Gb (fp16)
        #pragma unroll
        for (int mi = 0; mi < 2; mi++)
            #pragma unroll
            for (int ni = 0; ni < 4; ni++) {
                int r0 = wm * 32 + mi * 16 + gid;
                int cb = wn * 32 + ni * 8 + tig * 2;
                float bb0 = bm1[cc * 128 + cb], bb1 = bm1[cc * 128 + cb + 1];
                float t0 = tacc[mi][ni][0] + bb0;
                float t1 = tacc[mi][ni][1] + bb1;
                float t2 = tacc[mi][ni][2] + bb0;
                float t3 = tacc[mi][ni][3] + bb1;
                float s2 = 0.70710678118654752f;
                *(__half2*)(Gb + r0 * VSTR + cb) = __floats2half2_rn(
                    0.5f * t0 * (1.f + erff(t0 * s2)),
                    0.5f * t1 * (1.f + erff(t1 * s2)));
                *(__half2*)(Gb + (r0 + 8) * VSTR + cb) = __floats2half2_rn(
                    0.5f * t2 * (1.f + erff(t2 * s2)),
                    0.5f * t3 * (1.f + erff(t3 * s2)));
            }
        run_gemm<2>(Bb, Gb, VSTR, g_W2T, HIDN, cc * 128,
                    uacc, tid, wm, wn, lane);

        if (cc < 3) {   // prefetch next W1 tile chunk0
            issueB(Bb0, g_W1T + (cc + 1) * 128 * DD, DD, 0, tid);
            cp_commit();
        }
    }

    // ---------------- z = y + u + bm2 -> Yb (in place) -> out --------------
    #pragma unroll
    for (int mi = 0; mi < 2; mi++)
        #pragma unroll
        for (int ni = 0; ni < 4; ni++) {
            int r0 = wm * 32 + mi * 16 + gid;
            int cb = wn * 32 + ni * 8 + tig * 2;
            Yb[r0 * YSTR + cb]         += uacc[mi][ni][0] + bm2[cb];
            Yb[r0 * YSTR + cb + 1]     += uacc[mi][ni][1] + bm2[cb + 1];
            Yb[(r0 + 8) * YSTR + cb]   += uacc[mi][ni][2] + bm2[cb];
            Yb[(r0 + 8) * YSTR + cb+1] += uacc[mi][ni][3] + bm2[cb + 1];
        }
    __syncthreads();
    #pragma unroll
    for (int i = 0; i < 8; i++) {
        int idx = tid + NTHR * i;            // 2048 float4
        int row = idx >> 5;
        int c   = (idx & 31) * 4;
        float4 v4 = *(const float4*)(Yb + row * YSTR + c);
        *(float4*)(out + (tile0 + row) * DD + c) = v4;
    }
}

// ------------------------------ launcher ----------------------------------
extern "C" void kernel_launch(void* const* d_in, const int* in_sizes, int n_in,
                              void* d_out, int out_size)
{
    const float* x   = (const float*)d_in[0];
    const float* g1  = (const float*)d_in[1];
    const float* b1  = (const float*)d_in[2];
    // d_in[3]=Wq, d_in[4]=bq, d_in[7]=rpb : dead
    const float* Wkv = (const float*)d_in[5];
    const float* bkv = (const float*)d_in[6];
    const float* Wp  = (const float*)d_in[8];
    const float* bp  = (const float*)d_in[9];
    const float* g2  = (const float*)d_in[10];
    const float* b2  = (const float*)d_in[11];
    const float* W1  = (const float*)d_in[12];
    const float* bm1 = (const float*)d_in[13];
    const float* W2  = (const float*)d_in[14];
    const float* bm2 = (const float*)d_in[15];
    float* out = (float*)d_out;

    cudaFuncSetAttribute(fused_mma,
                         cudaFuncAttributeMaxDynamicSharedMemorySize,
                         SMEM_BYTES);

    prep_kernel<<<192, 256>>>(Wkv, Wp, W1, W2);

    const int tokens = in_sizes[0] / CC;   // 65536
    const int grid   = tokens / MT;        // 1024
    fused_mma<<<grid, NTHR, SMEM_BYTES>>>(
        x, g1, b1, bkv, bp, g2, b2, bm1, bm2, out);
}

// round 6
// speedup vs baseline: 7.9752x; 1.0473x over previous
#include <cuda_runtime.h>
#include <cuda_fp16.h>
#include <math.h>
#include <stdint.h>

// ===========================================================================
// Live math (softmax over size-1 axis == 1 kills q/Wq/bq/rpb/k-half of Wkv):
//   h = LN(x;g1,b1); v = h@Wv+bv; y = v@Wp+bp;
//   z = y + gelu(LN(y;g2,b2)@W1+bm1)@W2 + bm2
// mma.sync m16n8k16 fp16 (fp32 accum), ldmatrix, single-shot K=128 B tiles
// with cross-phase cp.async prefetch.  64 tokens/CTA, 8 warps, 2 CTAs/SM.
// ===========================================================================

#define CC    384
#define DD    128
#define HIDN  512
#define MT    64
#define NTHR  256
#define EPSV  1e-5f

#define BSTR  72     // K=64 chunk stride (halves); row step 144B -> ldsm-clean
#define WSTR  136    // K=128 tile stride (halves); row step 272B -> ldsm-clean
#define VSTR  136
#define YSTR  132

// smem byte offsets
#define OFF_BB   0                    // B region: max(2x128x72, 128x136)x2 = 36864
#define OFF_VB   36864                // v / lny : 64 x 136 fp16 = 17408
#define OFF_GB   54272                // gelu    : 64 x 136 fp16 (A-chunk aliases)
#define OFF_YB   71680                // y       : 64 x 132 fp32 = 33792
#define OFF_MEAN 105472
#define OFF_RSTD 105728
#define SMEM_BYTES 105984

// Pre-transposed fp16 weights, [n][k] row-major (mma row.col B operand)
__device__ __half g_WvT[DD * CC];
__device__ __half g_WpT[DD * DD];
__device__ __half g_W1T[HIDN * DD];
__device__ __half g_W2T[DD * HIDN];

__device__ __forceinline__ uint32_t smem_u32(const void* p) {
    uint32_t a;
    asm("{ .reg .u64 t; cvta.to.shared.u64 t, %1; cvt.u32.u64 %0, t; }"
        : "=r"(a) : "l"(p));
    return a;
}
__device__ __forceinline__ void cp16(uint32_t dst, const void* src) {
    asm volatile("cp.async.cg.shared.global [%0], [%1], 16;"
                 :: "r"(dst), "l"(src));
}
__device__ __forceinline__ void cp_commit() {
    asm volatile("cp.async.commit_group;" ::: "memory");
}
template<int N> __device__ __forceinline__ void cp_wait() {
    asm volatile("cp.async.wait_group %0;" :: "n"(N) : "memory");
}
__device__ __forceinline__ void ldsm4(uint32_t r[4], uint32_t addr) {
    asm volatile("ldmatrix.sync.aligned.m8n8.x4.shared.b16 {%0,%1,%2,%3}, [%4];"
                 : "=r"(r[0]), "=r"(r[1]), "=r"(r[2]), "=r"(r[3]) : "r"(addr));
}
__device__ __forceinline__ void mma16(float c[4],
    uint32_t a0, uint32_t a1, uint32_t a2, uint32_t a3,
    uint32_t b0, uint32_t b1) {
    asm volatile(
        "mma.sync.aligned.m16n8k16.row.col.f32.f16.f16.f32 "
        "{%0,%1,%2,%3}, {%4,%5,%6,%7}, {%8,%9}, {%0,%1,%2,%3};"
        : "+f"(c[0]), "+f"(c[1]), "+f"(c[2]), "+f"(c[3])
        : "r"(a0), "r"(a1), "r"(a2), "r"(a3), "r"(b0), "r"(b1));
}

// Fast exact-erf gelu (A&S 7.1.26, abs err ~1.5e-7; MUFU rcp/ex2)
__device__ __forceinline__ float gelu_f(float v) {
    float x = fabsf(v) * 0.70710678118654752f;
    float w = __fdividef(1.f, fmaf(0.3275911f, x, 1.f));
    float p = fmaf(w, 1.061405429f, -1.453152027f);
    p = fmaf(p, w, 1.421413741f);
    p = fmaf(p, w, -0.284496736f);
    p = fmaf(p, w, 0.254829592f);
    p *= w;
    float e = __expf(-x * x);
    float er = fmaf(-p, e, 1.f);
    return 0.5f * v * (1.f + copysignf(er, v));
}

// ----- MMA bodies ---------------------------------------------------------
#define MMA_KSTEP(acc, aA0, aA1, aB0, aB1, koff) { \
    uint32_t a0[4], a1[4], b0[4], b1[4]; \
    ldsm4(a0, (aA0) + (koff)); ldsm4(a1, (aA1) + (koff)); \
    ldsm4(b0, (aB0) + (koff)); ldsm4(b1, (aB1) + (koff)); \
    mma16(acc[0][0], a0[0],a0[1],a0[2],a0[3], b0[0], b0[2]); \
    mma16(acc[0][1], a0[0],a0[1],a0[2],a0[3], b0[1], b0[3]); \
    mma16(acc[0][2], a0[0],a0[1],a0[2],a0[3], b1[0], b1[2]); \
    mma16(acc[0][3], a0[0],a0[1],a0[2],a0[3], b1[1], b1[3]); \
    mma16(acc[1][0], a1[0],a1[1],a1[2],a1[3], b0[0], b0[2]); \
    mma16(acc[1][1], a1[0],a1[1],a1[2],a1[3], b0[1], b0[3]); \
    mma16(acc[1][2], a1[0],a1[1],a1[2],a1[3], b1[0], b1[2]); \
    mma16(acc[1][3], a1[0],a1[1],a1[2],a1[3], b1[1], b1[3]); \
}

// K=64 chunk (stage 2): A stride lda, B stride BSTR
__device__ __forceinline__ void mma_chunk64(
    const __half* As, int lda, const __half* Bs,
    float acc[2][4][4], int wm, int wn, int lane)
{
    const int lrow = lane & 15;
    const int lcol = (lane >> 4) << 3;
    uint32_t aA0 = smem_u32(As + (wm * 32 +      lrow) * lda + lcol);
    uint32_t aA1 = smem_u32(As + (wm * 32 + 16 + lrow) * lda + lcol);
    uint32_t aB0 = smem_u32(Bs + (wn * 32 +      lrow) * BSTR + lcol);
    uint32_t aB1 = smem_u32(Bs + (wn * 32 + 16 + lrow) * BSTR + lcol);
    #pragma unroll
    for (int k0 = 0; k0 < 64; k0 += 16)
        MMA_KSTEP(acc, aA0, aA1, aB0, aB1, k0 * 2);
}

// K=128 GEMM: A stride VSTR, B stride WSTR (single tile)
__device__ __forceinline__ void mma_gemm128(
    const __half* As, const __half* Bs,
    float acc[2][4][4], int wm, int wn, int lane)
{
    const int lrow = lane & 15;
    const int lcol = (lane >> 4) << 3;
    uint32_t aA0 = smem_u32(As + (wm * 32 +      lrow) * VSTR + lcol);
    uint32_t aA1 = smem_u32(As + (wm * 32 + 16 + lrow) * VSTR + lcol);
    uint32_t aB0 = smem_u32(Bs + (wn * 32 +      lrow) * WSTR + lcol);
    uint32_t aB1 = smem_u32(Bs + (wn * 32 + 16 + lrow) * WSTR + lcol);
    #pragma unroll
    for (int k0 = 0; k0 < 128; k0 += 16)
        MMA_KSTEP(acc, aA0, aA1, aB0, aB1, k0 * 2);
}

// ----- async B loaders ----------------------------------------------------
// K=64 chunk: 128 rows x 64 halves of Wg[n][ldw] starting col kc
__device__ __forceinline__ void issueB64(__half* Bdst, const __half* __restrict__ Wg,
                                         int ldw, int kc, int tid)
{
    #pragma unroll
    for (int i = 0; i < 4; i++) {
        int idx = tid + NTHR * i;
        int row = idx >> 3;
        int g8  = (idx & 7) << 3;
        cp16(smem_u32(Bdst + row * BSTR + g8), Wg + row * ldw + kc + g8);
    }
}
// K=128 tile: 128 rows x 128 halves of Wg[n][ldw]
__device__ __forceinline__ void issueB128(__half* Bdst, const __half* __restrict__ Wg,
                                          int ldw, int tid)
{
    #pragma unroll
    for (int i = 0; i < 8; i++) {
        int idx = tid + NTHR * i;
        int row = idx >> 4;
        int g8  = (idx & 15) << 3;
        cp16(smem_u32(Bdst + row * WSTR + g8), Wg + row * ldw + g8);
    }
}

#define ZERO_ACC(A) { _Pragma("unroll") for (int _m=0;_m<2;_m++) \
    _Pragma("unroll") for (int _n=0;_n<4;_n++) \
    _Pragma("unroll") for (int _q=0;_q<4;_q++) (A)[_m][_n][_q] = 0.f; }

// --------------------------- weight prep kernel ---------------------------
__global__ void prep_kernel(const float* __restrict__ Wkv,
                            const float* __restrict__ Wp,
                            const float* __restrict__ W1,
                            const float* __restrict__ W2) {
    int tid = blockIdx.x * blockDim.x + threadIdx.x;
    int str = gridDim.x * blockDim.x;
    for (int s = tid; s < CC * DD; s += str) {
        int k = s / DD, n = s % DD;
        g_WvT[n * CC + k] = __float2half_rn(Wkv[k * 256 + 128 + n]);
    }
    for (int s = tid; s < DD * DD; s += str) {
        int k = s / DD, n = s % DD;
        g_WpT[n * DD + k] = __float2half_rn(Wp[k * DD + n]);
    }
    for (int s = tid; s < DD * HIDN; s += str) {
        int k = s / HIDN, n = s % HIDN;
        g_W1T[n * DD + k] = __float2half_rn(W1[k * HIDN + n]);
    }
    for (int s = tid; s < HIDN * DD; s += str) {
        int k = s / DD, n = s % DD;
        g_W2T[n * HIDN + k] = __float2half_rn(W2[k * DD + n]);
    }
}

// ------------------------------ main kernel -------------------------------
extern __shared__ char smem_raw[];

__global__ void __launch_bounds__(NTHR, 2) fused_mma(
    const float* __restrict__ x,
    const float* __restrict__ g1, const float* __restrict__ b1,
    const float* __restrict__ bkv, const float* __restrict__ bp,
    const float* __restrict__ g2, const float* __restrict__ b2,
    const float* __restrict__ bm1, const float* __restrict__ bm2,
    float* __restrict__ out)
{
    __half* Bb0 = (__half*)(smem_raw + OFF_BB);
    __half* Bb1 = Bb0 + 128 * BSTR;
    __half* Bw  = Bb0;                           // K=128 tile (same region)
    __half* Vb  = (__half*)(smem_raw + OFF_VB);
    __half* Gb  = (__half*)(smem_raw + OFF_GB);
    __half* Ab  = (__half*)(smem_raw + OFF_GB);  // alias: stage-2 only
    float*  Yb  = (float*)(smem_raw + OFF_YB);
    float* smean = (float*)(smem_raw + OFF_MEAN);
    float* srstd = (float*)(smem_raw + OFF_RSTD);

    const int tid  = threadIdx.x;
    const int lane = tid & 31;
    const int warp = tid >> 5;
    const int wm   = warp >> 2;      // 0..1 (M tile)
    const int wn   = warp & 3;       // 0..3 (N tile)
    const int gid  = lane >> 2;      // 0..7
    const int tig  = lane & 3;       // 0..3
    const long tile0 = (long)blockIdx.x * MT;

    // Prefetch first Wv B-chunk: hides under LN stats.
    issueB64(Bb0, g_WvT, CC, 0, tid); cp_commit();

    // ---------------- LN(x) stats (8 rows per warp) ----------------
    #pragma unroll 1
    for (int i = 0; i < 8; i++) {
        int row = warp * 8 + i;
        const float* xr = x + (tile0 + row) * CC;
        float s = 0.f, ss = 0.f;
        #pragma unroll
        for (int u = 0; u < 12; u++) {
            float t = xr[lane + 32 * u];
            s += t; ss += t * t;
        }
        #pragma unroll
        for (int o = 16; o > 0; o >>= 1) {
            s  += __shfl_xor_sync(0xffffffffu, s,  o);
            ss += __shfl_xor_sync(0xffffffffu, ss, o);
        }
        if (lane == 0) {
            float m = s * (1.f / 384.f);
            float v = ss * (1.f / 384.f) - m * m;
            smean[row] = m;
            srstd[row] = rsqrtf(v + EPSV);
        }
    }
    __syncthreads();

    // ---------------- v = LN(x) @ WvT  (K=384, 6 x K=64 chunks) -----------
    float vacc[2][4][4];
    ZERO_ACC(vacc);
    #pragma unroll 1
    for (int c = 0; c < 6; c++) {
        __half* Bcur = (c & 1) ? Bb1 : Bb0;
        if (c < 5) {
            issueB64((c & 1) ? Bb0 : Bb1, g_WvT, CC, (c + 1) * 64, tid);
            cp_commit();
        }
        // fill A chunk: normalize x[:, kc..kc+63] -> fp16 (float4 loads)
        int kc = c * 64;
        #pragma unroll
        for (int i = 0; i < 4; i++) {
            int idx = tid + NTHR * i;            // 64 rows x 16 quads
            int row = idx >> 4, q = (idx & 15) * 4;
            int k = kc + q;
            float4 xx = *(const float4*)(x + (tile0 + row) * CC + k);
            float4 gg = *(const float4*)(g1 + k);
            float4 bb = *(const float4*)(b1 + k);
            float m = smean[row], rs = srstd[row];
            __half2 h0 = __floats2half2_rn(fmaf((xx.x - m) * rs, gg.x, bb.x),
                                           fmaf((xx.y - m) * rs, gg.y, bb.y));
            __half2 h1 = __floats2half2_rn(fmaf((xx.z - m) * rs, gg.z, bb.z),
                                           fmaf((xx.w - m) * rs, gg.w, bb.w));
            uint2 pk = make_uint2(*(uint32_t*)&h0, *(uint32_t*)&h1);
            *(uint2*)(Ab + row * BSTR + q) = pk;
        }
        if (c < 5) cp_wait<1>(); else cp_wait<0>();
        __syncthreads();
        mma_chunk64(Ab, BSTR, Bcur, vacc, wm, wn, lane);
        __syncthreads();
    }

    // Prefetch full Wp tile: hides under v epilogue.
    issueB128(Bw, g_WpT, DD, tid); cp_commit();

    // v epilogue -> Vb (fp16)
    #pragma unroll
    for (int mi = 0; mi < 2; mi++)
        #pragma unroll
        for (int ni = 0; ni < 4; ni++) {
            int r0 = wm * 32 + mi * 16 + gid;
            int cb = wn * 32 + ni * 8 + tig * 2;
            float b0 = bkv[128 + cb], b1v = bkv[129 + cb];
            *(__half2*)(Vb + r0 * VSTR + cb) =
                __floats2half2_rn(vacc[mi][ni][0] + b0, vacc[mi][ni][1] + b1v);
            *(__half2*)(Vb + (r0 + 8) * VSTR + cb) =
                __floats2half2_rn(vacc[mi][ni][2] + b0, vacc[mi][ni][3] + b1v);
        }

    // ---------------- y = v @ WpT (K=128, single tile) ----------------
    float yacc[2][4][4];
    ZERO_ACC(yacc);
    cp_wait<0>();
    __syncthreads();                 // Wp ready; Vb published
    mma_gemm128(Vb, Bw, yacc, wm, wn, lane);
    __syncthreads();

    // Prefetch W1 tile0: hides under y epilogue + LN(y).
    issueB128(Bw, g_W1T, DD, tid); cp_commit();

    // y epilogue -> Yb (fp32)
    #pragma unroll
    for (int mi = 0; mi < 2; mi++)
        #pragma unroll
        for (int ni = 0; ni < 4; ni++) {
            int r0 = wm * 32 + mi * 16 + gid;
            int cb = wn * 32 + ni * 8 + tig * 2;
            Yb[r0 * YSTR + cb]         = yacc[mi][ni][0] + bp[cb];
            Yb[r0 * YSTR + cb + 1]     = yacc[mi][ni][1] + bp[cb + 1];
            Yb[(r0 + 8) * YSTR + cb]   = yacc[mi][ni][2] + bp[cb];
            Yb[(r0 + 8) * YSTR + cb+1] = yacc[mi][ni][3] + bp[cb + 1];
        }
    __syncthreads();                 // publish Yb

    // lny = LN(y) -> Vb (fp16)
    #pragma unroll 1
    for (int i = 0; i < 8; i++) {
        int row = warp * 8 + i;
        float vals[4];
        float s = 0.f, ss = 0.f;
        #pragma unroll
        for (int u = 0; u < 4; u++) {
            float t = Yb[row * YSTR + lane + 32 * u];
            vals[u] = t; s += t; ss += t * t;
        }
        #pragma unroll
        for (int o = 16; o > 0; o >>= 1) {
            s  += __shfl_xor_sync(0xffffffffu, s,  o);
            ss += __shfl_xor_sync(0xffffffffu, ss, o);
        }
        float m  = s * (1.f / 128.f);
        float vv = ss * (1.f / 128.f) - m * m;
        float rs = rsqrtf(vv + EPSV);
        #pragma unroll
        for (int u = 0; u < 4; u++) {
            int k = lane + 32 * u;
            Vb[row * VSTR + k] =
                __float2half_rn((vals[u] - m) * rs * g2[k] + b2[k]);
        }
    }

    // ---------------- MLP: 4 hidden tiles of 128 ----------------
    float uacc[2][4][4];
    ZERO_ACC(uacc);
    #pragma unroll 1
    for (int cc = 0; cc < 4; cc++) {
        cp_wait<0>();
        __syncthreads();             // W1(cc) ready; lny/Gb published
        float tacc[2][4][4];
        ZERO_ACC(tacc);
        mma_gemm128(Vb, Bw, tacc, wm, wn, lane);
        __syncthreads();

        issueB128(Bw, g_W2T + cc * 128, HIDN, tid); cp_commit();

        // gelu epilogue -> Gb (fp16)
        #pragma unroll
        for (int mi = 0; mi < 2; mi++)
            #pragma unroll
            for (int ni = 0; ni < 4; ni++) {
                int r0 = wm * 32 + mi * 16 + gid;
                int cb = wn * 32 + ni * 8 + tig * 2;
                float bb0 = bm1[cc * 128 + cb], bb1 = bm1[cc * 128 + cb + 1];
                *(__half2*)(Gb + r0 * VSTR + cb) = __floats2half2_rn(
                    gelu_f(tacc[mi][ni][0] + bb0),
                    gelu_f(tacc[mi][ni][1] + bb1));
                *(__half2*)(Gb + (r0 + 8) * VSTR + cb) = __floats2half2_rn(
                    gelu_f(tacc[mi][ni][2] + bb0),
                    gelu_f(tacc[mi][ni][3] + bb1));
            }
        cp_wait<0>();
        __syncthreads();             // W2(cc) ready; Gb published
        mma_gemm128(Gb, Bw, uacc, wm, wn, lane);
        __syncthreads();

        if (cc < 3) {
            issueB128(Bw, g_W1T + (cc + 1) * 128 * DD, DD, tid);
            cp_commit();
        }
    }

    // ---------------- z = y + u + bm2 -> direct global store --------------
    #pragma unroll
    for (int mi = 0; mi < 2; mi++)
        #pragma unroll
        for (int ni = 0; ni < 4; ni++) {
            int r0 = wm * 32 + mi * 16 + gid;
            int cb = wn * 32 + ni * 8 + tig * 2;
            float bb0 = bm2[cb], bb1 = bm2[cb + 1];
            float2 z0, z1;
            z0.x = Yb[r0 * YSTR + cb]       + uacc[mi][ni][0] + bb0;
            z0.y = Yb[r0 * YSTR + cb + 1]   + uacc[mi][ni][1] + bb1;
            z1.x = Yb[(r0+8) * YSTR + cb]   + uacc[mi][ni][2] + bb0;
            z1.y = Yb[(r0+8) * YSTR + cb+1] + uacc[mi][ni][3] + bb1;
            *(float2*)(out + (tile0 + r0) * DD + cb)     = z0;
            *(float2*)(out + (tile0 + r0 + 8) * DD + cb) = z1;
        }
}

// ------------------------------ launcher ----------------------------------
extern "C" void kernel_launch(void* const* d_in, const int* in_sizes, int n_in,
                              void* d_out, int out_size)
{
    const float* x   = (const float*)d_in[0];
    const float* g1  = (const float*)d_in[1];
    const float* b1  = (const float*)d_in[2];
    // d_in[3]=Wq, d_in[4]=bq, d_in[7]=rpb : dead
    const float* Wkv = (const float*)d_in[5];
    const float* bkv = (const float*)d_in[6];
    const float* Wp  = (const float*)d_in[8];
    const float* bp  = (const float*)d_in[9];
    const float* g2  = (const float*)d_in[10];
    const float* b2  = (const float*)d_in[11];
    const float* W1  = (const float*)d_in[12];
    const float* bm1 = (const float*)d_in[13];
    const float* W2  = (const float*)d_in[14];
    const float* bm2 = (const float*)d_in[15];
    float* out = (float*)d_out;

    cudaFuncSetAttribute(fused_mma,
                         cudaFuncAttributeMaxDynamicSharedMemorySize,
                         SMEM_BYTES);

    prep_kernel<<<192, 256>>>(Wkv, Wp, W1, W2);

    const int tokens = in_sizes[0] / CC;   // 65536
    const int grid   = tokens / MT;        // 1024
    fused_mma<<<grid, NTHR, SMEM_BYTES>>>(
        x, g1, b1, bkv, bp, g2, b2, bm1, bm2, out);
}